// round 1
// baseline (speedup 1.0000x reference)
#include <cuda_runtime.h>

// Problem constants
#define B_TOT   8192
#define NNODE   17
#define CIN     256
#define COUT    256

// Tiling
#define TB       8                 // batches per CTA
#define BM       (TB * NNODE)      // 136 real rows
#define BMP      144               // padded to multiple of 16
#define KC       16                // K chunk
#define NKT      (CIN / KC)        // 16 chunks
#define XS_LD    20                // smem stride for x tile (conflict-free A-frag loads)
#define WS_LD    264               // smem stride for w tile (conflict-free B-frag loads)
#define GS_LD    264               // smem stride for g tile
#define NTHREADS 384               // 12 warps: 3 (M) x 4 (N)

#define SMEM_FLOATS (BMP * GS_LD + NNODE * NNODE + 128)
#define SMEM_BYTES  (SMEM_FLOATS * 4)

__device__ float g_Asym[NNODE * NNODE];

// Symmetrize A = 0.5 * ((adj + adj2) + (adj + adj2)^T)
__global__ void mgc_prep(const float* __restrict__ adj, const float* __restrict__ adj2) {
    int e = threadIdx.x;
    if (e < NNODE * NNODE) {
        int i = e / NNODE, j = e % NNODE;
        float a = adj[i * NNODE + j] + adj2[i * NNODE + j];
        float b = adj[j * NNODE + i] + adj2[j * NNODE + i];
        g_Asym[e] = 0.5f * (a + b);
    }
}

// Fused: H0 = X@W0, H1 = X@W1 (tf32 mma), g = M*H, out = A-mix(g) + bias
__global__ void __launch_bounds__(NTHREADS, 1)
mgc_main(const float* __restrict__ x, const float* __restrict__ W,
         const float* __restrict__ Mm, const float* __restrict__ bias,
         float* __restrict__ out) {
    extern __shared__ unsigned smem_u[];

    const int tid  = threadIdx.x;
    const int lane = tid & 31;
    const int warp = tid >> 5;
    const int gid  = lane >> 2;   // groupID (0..7)
    const int tig  = lane & 3;    // threadID in group (0..3)
    const int wm   = warp % 3;    // warp row (M)
    const int wn   = warp / 3;    // warp col (N)
    const int b0row = blockIdx.x * BM;       // first global row (b*17+j flattened)
    const int d0    = blockIdx.y * 128;      // output-channel half

    // Shared memory layout (phase 1 region reused by phase 2's gs rows 0..53):
    unsigned* xs = smem_u;                          // [2][BMP][XS_LD] = 5760 u32
    unsigned* ws = smem_u + 2 * BMP * XS_LD;        // [2][KC][WS_LD]  = 8448 u32 (ends 14208)
    float* fs = reinterpret_cast<float*>(smem_u);
    float* gs = fs;                                 // [BMP][GS_LD] = 38016 floats
    float* As = fs + BMP * GS_LD;                   // 289 floats (beyond phase-1 region)
    float* bs = As + NNODE * NNODE;                 // 128 floats

    for (int e = tid; e < NNODE * NNODE; e += NTHREADS) As[e] = g_Asym[e];
    for (int e = tid; e < 128; e += NTHREADS) bs[e] = __ldg(&bias[d0 + e]);

    float acc[3][8][4];
#pragma unroll
    for (int i = 0; i < 3; i++)
#pragma unroll
        for (int j = 0; j < 8; j++)
#pragma unroll
            for (int q = 0; q < 4; q++) acc[i][j][q] = 0.f;

    float xr[6], wr[11];

    auto ld_tile = [&](int kt) {
        const int k = kt * KC;
#pragma unroll
        for (int i = 0; i < 6; i++) {
            int e = tid + i * NTHREADS;               // < 2304
            int r = e >> 4, c = e & 15;
            xr[i] = (r < BM) ? __ldg(&x[(b0row + r) * CIN + k + c]) : 0.f;
        }
#pragma unroll
        for (int i = 0; i < 11; i++) {
            int e = tid + i * NTHREADS;
            if (e < KC * 256) {
                int kr = e >> 8, n = e & 255;
                int mat = n >> 7;
                wr[i] = __ldg(&W[mat * (CIN * COUT) + (k + kr) * COUT + d0 + (n & 127)]);
            }
        }
    };

    auto st_tile = [&](int buf) {
        unsigned* xb = xs + buf * (BMP * XS_LD);
        unsigned* wb = ws + buf * (KC * WS_LD);
#pragma unroll
        for (int i = 0; i < 6; i++) {
            int e = tid + i * NTHREADS;
            int r = e >> 4, c = e & 15;
            unsigned u; asm("cvt.rna.tf32.f32 %0, %1;" : "=r"(u) : "f"(xr[i]));
            xb[r * XS_LD + c] = u;
        }
#pragma unroll
        for (int i = 0; i < 11; i++) {
            int e = tid + i * NTHREADS;
            if (e < KC * 256) {
                int kr = e >> 8, n = e & 255;
                unsigned u; asm("cvt.rna.tf32.f32 %0, %1;" : "=r"(u) : "f"(wr[i]));
                wb[kr * WS_LD + n] = u;
            }
        }
    };

    auto do_mma = [&](int buf) {
        const unsigned* xb = xs + buf * (BMP * XS_LD);
        const unsigned* wb = ws + buf * (KC * WS_LD);
#pragma unroll
        for (int s = 0; s < 2; s++) {
            const int k8 = s * 8;
            unsigned a[3][4], bfr[8][2];
#pragma unroll
            for (int mt = 0; mt < 3; mt++) {
                int r0 = wm * 48 + mt * 16 + gid;
                a[mt][0] = xb[r0 * XS_LD + k8 + tig];
                a[mt][1] = xb[(r0 + 8) * XS_LD + k8 + tig];
                a[mt][2] = xb[r0 * XS_LD + k8 + tig + 4];
                a[mt][3] = xb[(r0 + 8) * XS_LD + k8 + tig + 4];
            }
#pragma unroll
            for (int nf = 0; nf < 8; nf++) {
                int c0 = wn * 64 + nf * 8 + gid;
                bfr[nf][0] = wb[(k8 + tig) * WS_LD + c0];
                bfr[nf][1] = wb[(k8 + tig + 4) * WS_LD + c0];
            }
#pragma unroll
            for (int mt = 0; mt < 3; mt++)
#pragma unroll
                for (int nf = 0; nf < 8; nf++)
                    asm volatile(
                        "mma.sync.aligned.m16n8k8.row.col.f32.tf32.tf32.f32 "
                        "{%0,%1,%2,%3}, {%4,%5,%6,%7}, {%8,%9}, {%0,%1,%2,%3};"
                        : "+f"(acc[mt][nf][0]), "+f"(acc[mt][nf][1]),
                          "+f"(acc[mt][nf][2]), "+f"(acc[mt][nf][3])
                        : "r"(a[mt][0]), "r"(a[mt][1]), "r"(a[mt][2]), "r"(a[mt][3]),
                          "r"(bfr[nf][0]), "r"(bfr[nf][1]));
        }
    };

    // --- Main K loop: reg-staged double buffer ---
    ld_tile(0);
    st_tile(0);
    __syncthreads();
    for (int kt = 0; kt < NKT; kt++) {
        if (kt + 1 < NKT) ld_tile(kt + 1);
        do_mma(kt & 1);
        if (kt + 1 < NKT) {
            __syncthreads();
            st_tile((kt + 1) & 1);
            __syncthreads();
        }
    }
    __syncthreads();   // all warps done with xs/ws before gs overwrites them

    // --- Epilogue: g = M * H into smem (cols 0..127 = g0, 128..255 = g1) ---
#pragma unroll
    for (int mt = 0; mt < 3; mt++) {
        int r0 = wm * 48 + mt * 16 + gid;
        int j0 = r0 % NNODE;
        int j1 = (r0 + 8) % NNODE;
#pragma unroll
        for (int nf = 0; nf < 8; nf++) {
            int c0 = wn * 64 + nf * 8 + 2 * tig;
            int dd = d0 + (c0 & 127);
            float m00 = __ldg(&Mm[j0 * COUT + dd]);
            float m01 = __ldg(&Mm[j0 * COUT + dd + 1]);
            float m10 = __ldg(&Mm[j1 * COUT + dd]);
            float m11 = __ldg(&Mm[j1 * COUT + dd + 1]);
            gs[r0 * GS_LD + c0]           = acc[mt][nf][0] * m00;
            gs[r0 * GS_LD + c0 + 1]       = acc[mt][nf][1] * m01;
            gs[(r0 + 8) * GS_LD + c0]     = acc[mt][nf][2] * m10;
            gs[(r0 + 8) * GS_LD + c0 + 1] = acc[mt][nf][3] * m11;
        }
    }
    __syncthreads();

    // --- Mixing: out[i,d] = sum_j A[i,j]*g1[j,d] + A[i,i]*(g0[i,d]-g1[i,d]) + bias ---
    for (int e = tid; e < BM * 128; e += NTHREADS) {
        int r = e >> 7, dn = e & 127;
        int i = r % NNODE;
        int rb = r - i;                  // base row of this batch
        const float* Ai = As + i * NNODE;
        float v = 0.f;
#pragma unroll
        for (int j = 0; j < NNODE; j++)
            v = fmaf(Ai[j], gs[(rb + j) * GS_LD + 128 + dn], v);
        v = fmaf(Ai[i], gs[r * GS_LD + dn] - gs[r * GS_LD + 128 + dn], v);
        out[(b0row + r) * COUT + d0 + dn] = v + bs[dn];
    }
}

extern "C" void kernel_launch(void* const* d_in, const int* in_sizes, int n_in,
                              void* d_out, int out_size) {
    const float* x    = (const float*)d_in[0];
    const float* W    = (const float*)d_in[1];
    const float* Mm   = (const float*)d_in[2];
    const float* adj  = (const float*)d_in[3];
    const float* adj2 = (const float*)d_in[4];
    const float* bias = (const float*)d_in[5];
    float* out = (float*)d_out;

    (void)in_sizes; (void)n_in; (void)out_size;

    cudaFuncSetAttribute(mgc_main, cudaFuncAttributeMaxDynamicSharedMemorySize, SMEM_BYTES);

    mgc_prep<<<1, NNODE * NNODE>>>(adj, adj2);
    dim3 grid(B_TOT / TB, 2);
    mgc_main<<<grid, NTHREADS, SMEM_BYTES>>>(x, W, Mm, bias, out);
}

// round 2
// speedup vs baseline: 1.0018x; 1.0018x over previous
#include <cuda_runtime.h>

// Problem constants
#define B_TOT   8192
#define NNODE   17
#define CIN     256
#define COUT    256

// Tiling
#define TB       8                 // batches per CTA
#define BM       (TB * NNODE)      // 136 real rows
#define BMP      144               // padded to multiple of 16
#define KC       16                // K chunk
#define NKT      (CIN / KC)        // 16 chunks
#define XS_LD    20                // smem stride for x tile (conflict-free A-frag loads)
#define WS_LD    264               // smem stride for w tile (conflict-free B-frag loads)
#define GS_LD    264               // smem stride for g tile
#define NTHREADS 384               // 12 warps: 3 (M) x 4 (N)

#define SMEM_FLOATS (BMP * GS_LD + NNODE * NNODE + 128)
#define SMEM_BYTES  (SMEM_FLOATS * 4)

__device__ float g_Asym[NNODE * NNODE];

// Symmetrize A = 0.5 * ((adj + adj2) + (adj + adj2)^T)
__global__ void mgc_prep(const float* __restrict__ adj, const float* __restrict__ adj2) {
    int e = threadIdx.x;
    if (e < NNODE * NNODE) {
        int i = e / NNODE, j = e % NNODE;
        float a = adj[i * NNODE + j] + adj2[i * NNODE + j];
        float b = adj[j * NNODE + i] + adj2[j * NNODE + i];
        g_Asym[e] = 0.5f * (a + b);
    }
}

// Fused: H0 = X@W0, H1 = X@W1 (tf32 mma), g = M*H, out = A-mix(g) + bias
__global__ void __launch_bounds__(NTHREADS, 1)
mgc_main(const float* __restrict__ x, const float* __restrict__ W,
         const float* __restrict__ Mm, const float* __restrict__ bias,
         float* __restrict__ out) {
    extern __shared__ unsigned smem_u[];

    const int tid  = threadIdx.x;
    const int lane = tid & 31;
    const int warp = tid >> 5;
    const int gid  = lane >> 2;   // groupID (0..7)
    const int tig  = lane & 3;    // threadID in group (0..3)
    const int wm   = warp % 3;    // warp row (M)
    const int wn   = warp / 3;    // warp col (N)
    const int b0row = blockIdx.x * BM;       // first global row (b*17+j flattened)
    const int d0    = blockIdx.y * 128;      // output-channel half

    // Shared memory layout (phase 1 region reused by phase 2's gs rows 0..53):
    unsigned* xs = smem_u;                          // [2][BMP][XS_LD] = 5760 u32
    unsigned* ws = smem_u + 2 * BMP * XS_LD;        // [2][KC][WS_LD]  = 8448 u32 (ends 14208)
    float* fs = reinterpret_cast<float*>(smem_u);
    float* gs = fs;                                 // [BMP][GS_LD] = 38016 floats
    float* As = fs + BMP * GS_LD;                   // 289 floats (beyond phase-1 region)
    float* bs = As + NNODE * NNODE;                 // 128 floats

    for (int e = tid; e < NNODE * NNODE; e += NTHREADS) As[e] = g_Asym[e];
    for (int e = tid; e < 128; e += NTHREADS) bs[e] = __ldg(&bias[d0 + e]);

    float acc[3][8][4];
#pragma unroll
    for (int i = 0; i < 3; i++)
#pragma unroll
        for (int j = 0; j < 8; j++)
#pragma unroll
            for (int q = 0; q < 4; q++) acc[i][j][q] = 0.f;

    float xr[6], wr[11];

    auto ld_tile = [&](int kt) {
        const int k = kt * KC;
#pragma unroll
        for (int i = 0; i < 6; i++) {
            int e = tid + i * NTHREADS;               // < 2304
            int r = e >> 4, c = e & 15;
            xr[i] = (r < BM) ? __ldg(&x[(b0row + r) * CIN + k + c]) : 0.f;
        }
#pragma unroll
        for (int i = 0; i < 11; i++) {
            int e = tid + i * NTHREADS;
            if (e < KC * 256) {
                int kr = e >> 8, n = e & 255;
                int mat = n >> 7;
                wr[i] = __ldg(&W[mat * (CIN * COUT) + (k + kr) * COUT + d0 + (n & 127)]);
            }
        }
    };

    auto st_tile = [&](int buf) {
        unsigned* xb = xs + buf * (BMP * XS_LD);
        unsigned* wb = ws + buf * (KC * WS_LD);
#pragma unroll
        for (int i = 0; i < 6; i++) {
            int e = tid + i * NTHREADS;
            int r = e >> 4, c = e & 15;
            unsigned u; asm("cvt.rna.tf32.f32 %0, %1;" : "=r"(u) : "f"(xr[i]));
            xb[r * XS_LD + c] = u;
        }
#pragma unroll
        for (int i = 0; i < 11; i++) {
            int e = tid + i * NTHREADS;
            if (e < KC * 256) {
                int kr = e >> 8, n = e & 255;
                unsigned u; asm("cvt.rna.tf32.f32 %0, %1;" : "=r"(u) : "f"(wr[i]));
                wb[kr * WS_LD + n] = u;
            }
        }
    };

    auto do_mma = [&](int buf) {
        const unsigned* xb = xs + buf * (BMP * XS_LD);
        const unsigned* wb = ws + buf * (KC * WS_LD);
#pragma unroll
        for (int s = 0; s < 2; s++) {
            const int k8 = s * 8;
            unsigned a[3][4], bfr[8][2];
#pragma unroll
            for (int mt = 0; mt < 3; mt++) {
                int r0 = wm * 48 + mt * 16 + gid;
                a[mt][0] = xb[r0 * XS_LD + k8 + tig];
                a[mt][1] = xb[(r0 + 8) * XS_LD + k8 + tig];
                a[mt][2] = xb[r0 * XS_LD + k8 + tig + 4];
                a[mt][3] = xb[(r0 + 8) * XS_LD + k8 + tig + 4];
            }
#pragma unroll
            for (int nf = 0; nf < 8; nf++) {
                int c0 = wn * 64 + nf * 8 + gid;
                bfr[nf][0] = wb[(k8 + tig) * WS_LD + c0];
                bfr[nf][1] = wb[(k8 + tig + 4) * WS_LD + c0];
            }
#pragma unroll
            for (int mt = 0; mt < 3; mt++)
#pragma unroll
                for (int nf = 0; nf < 8; nf++)
                    asm volatile(
                        "mma.sync.aligned.m16n8k8.row.col.f32.tf32.tf32.f32 "
                        "{%0,%1,%2,%3}, {%4,%5,%6,%7}, {%8,%9}, {%0,%1,%2,%3};"
                        : "+f"(acc[mt][nf][0]), "+f"(acc[mt][nf][1]),
                          "+f"(acc[mt][nf][2]), "+f"(acc[mt][nf][3])
                        : "r"(a[mt][0]), "r"(a[mt][1]), "r"(a[mt][2]), "r"(a[mt][3]),
                          "r"(bfr[nf][0]), "r"(bfr[nf][1]));
        }
    };

    // --- Main K loop: reg-staged double buffer ---
    ld_tile(0);
    st_tile(0);
    __syncthreads();
    for (int kt = 0; kt < NKT; kt++) {
        if (kt + 1 < NKT) ld_tile(kt + 1);
        do_mma(kt & 1);
        if (kt + 1 < NKT) {
            __syncthreads();
            st_tile((kt + 1) & 1);
            __syncthreads();
        }
    }
    __syncthreads();   // all warps done with xs/ws before gs overwrites them

    // --- Epilogue: g = M * H into smem (cols 0..127 = g0, 128..255 = g1) ---
#pragma unroll
    for (int mt = 0; mt < 3; mt++) {
        int r0 = wm * 48 + mt * 16 + gid;
        int j0 = r0 % NNODE;
        int j1 = (r0 + 8) % NNODE;
#pragma unroll
        for (int nf = 0; nf < 8; nf++) {
            int c0 = wn * 64 + nf * 8 + 2 * tig;
            int dd = d0 + (c0 & 127);
            float m00 = __ldg(&Mm[j0 * COUT + dd]);
            float m01 = __ldg(&Mm[j0 * COUT + dd + 1]);
            float m10 = __ldg(&Mm[j1 * COUT + dd]);
            float m11 = __ldg(&Mm[j1 * COUT + dd + 1]);
            gs[r0 * GS_LD + c0]           = acc[mt][nf][0] * m00;
            gs[r0 * GS_LD + c0 + 1]       = acc[mt][nf][1] * m01;
            gs[(r0 + 8) * GS_LD + c0]     = acc[mt][nf][2] * m10;
            gs[(r0 + 8) * GS_LD + c0 + 1] = acc[mt][nf][3] * m11;
        }
    }
    __syncthreads();

    // --- Mixing: out[i,d] = sum_j A[i,j]*g1[j,d] + A[i,i]*(g0[i,d]-g1[i,d]) + bias ---
    for (int e = tid; e < BM * 128; e += NTHREADS) {
        int r = e >> 7, dn = e & 127;
        int i = r % NNODE;
        int rb = r - i;                  // base row of this batch
        const float* Ai = As + i * NNODE;
        float v = 0.f;
#pragma unroll
        for (int j = 0; j < NNODE; j++)
            v = fmaf(Ai[j], gs[(rb + j) * GS_LD + 128 + dn], v);
        v = fmaf(Ai[i], gs[r * GS_LD + dn] - gs[r * GS_LD + 128 + dn], v);
        out[(b0row + r) * COUT + d0 + dn] = v + bs[dn];
    }
}

extern "C" void kernel_launch(void* const* d_in, const int* in_sizes, int n_in,
                              void* d_out, int out_size) {
    const float* x    = (const float*)d_in[0];
    const float* W    = (const float*)d_in[1];
    const float* Mm   = (const float*)d_in[2];
    const float* adj  = (const float*)d_in[3];
    const float* adj2 = (const float*)d_in[4];
    const float* bias = (const float*)d_in[5];
    float* out = (float*)d_out;

    (void)in_sizes; (void)n_in; (void)out_size;

    cudaFuncSetAttribute(mgc_main, cudaFuncAttributeMaxDynamicSharedMemorySize, SMEM_BYTES);

    mgc_prep<<<1, NNODE * NNODE>>>(adj, adj2);
    dim3 grid(B_TOT / TB, 2);
    mgc_main<<<grid, NTHREADS, SMEM_BYTES>>>(x, W, Mm, bias, out);
}